// round 4
// baseline (speedup 1.0000x reference)
#include <cuda_runtime.h>
#include <math.h>

#define B 16
#define C 256
#define H 128
#define W 128
#define HW (H*W)
#define R 16

// Scratch (allocation-free: __device__ globals)
__device__ float g_avg[B*C];
__device__ float g_max[B*C];
__device__ float g_wch[B*C];
__device__ float g_cat[B*2*HW];   // [b][0]=maxmap, [b][1]=avgmap
__device__ float g_ws[B*HW];

// ---------------- K1: per-(b,c) mean & max over H,W ----------------
__global__ __launch_bounds__(256) void k_reduce_hw(const float* __restrict__ x) {
    int bc = blockIdx.x;                 // 0..B*C-1
    const float4* xp = (const float4*)(x + (size_t)bc * HW);
    float s = 0.f, m = -INFINITY;
    #pragma unroll 4
    for (int i = threadIdx.x; i < HW/4; i += blockDim.x) {
        float4 v = xp[i];
        s += (v.x + v.y) + (v.z + v.w);
        m = fmaxf(m, fmaxf(fmaxf(v.x, v.y), fmaxf(v.z, v.w)));
    }
    #pragma unroll
    for (int o = 16; o; o >>= 1) {
        s += __shfl_xor_sync(0xffffffffu, s, o);
        m = fmaxf(m, __shfl_xor_sync(0xffffffffu, m, o));
    }
    __shared__ float ss[8], sm[8];
    int w = threadIdx.x >> 5, l = threadIdx.x & 31;
    if (l == 0) { ss[w] = s; sm[w] = m; }
    __syncthreads();
    if (threadIdx.x == 0) {
        for (int i = 1; i < 8; i++) { s += ss[i]; m = fmaxf(m, sm[i]); }
        g_avg[bc] = s * (1.f / HW);
        g_max[bc] = m;
    }
}

// ---------------- K2: channel MLP -> wch ----------------
__global__ __launch_bounds__(256) void k_mlp(const float* __restrict__ w1, const float* __restrict__ b1,
                      const float* __restrict__ w2, const float* __restrict__ b2) {
    int b = blockIdx.x;
    int t = threadIdx.x;                 // 0..255 = channel
    __shared__ float s_avg[C], s_mx[C], s_h[R];
    s_avg[t] = g_avg[b*C + t];
    s_mx[t]  = g_max[b*C + t];
    __syncthreads();
    if (t < R) {
        float ha = b1[t], hm = b1[t];
        #pragma unroll 8
        for (int c = 0; c < C; c++) {
            float w = w1[t*C + c];
            ha += w * s_avg[c];
            hm += w * s_mx[c];
        }
        s_h[t] = fmaxf(ha, 0.f) + fmaxf(hm, 0.f);
    }
    __syncthreads();
    float o = 2.f * b2[t];
    #pragma unroll
    for (int r = 0; r < R; r++) o += w2[t*R + r] * s_h[r];
    g_wch[b*C + t] = 1.f / (1.f + __expf(-o));
}

// ---------------- K3: cat = [max_c(wch*x), mean_c(wch*x)] ----------------
__global__ __launch_bounds__(128) void k_cat(const float* __restrict__ x) {
    int b  = blockIdx.y;
    int p4 = blockIdx.x * blockDim.x + threadIdx.x;   // float4 index within HW
    __shared__ float sw[C];
    for (int i = threadIdx.x; i < C; i += blockDim.x) sw[i] = g_wch[b*C + i];
    __syncthreads();
    const float4* xb = (const float4*)(x + (size_t)b * C * HW);
    float4 s = make_float4(0.f, 0.f, 0.f, 0.f);
    float4 m = make_float4(-INFINITY, -INFINITY, -INFINITY, -INFINITY);
    #pragma unroll 8
    for (int c = 0; c < C; c++) {
        float4 v = __ldg(&xb[(size_t)c * (HW/4) + p4]);
        float w = sw[c];
        float a0 = w*v.x, a1 = w*v.y, a2 = w*v.z, a3 = w*v.w;
        s.x += a0; s.y += a1; s.z += a2; s.w += a3;
        m.x = fmaxf(m.x, a0); m.y = fmaxf(m.y, a1);
        m.z = fmaxf(m.z, a2); m.w = fmaxf(m.w, a3);
    }
    const float inv = 1.f / C;
    s.x *= inv; s.y *= inv; s.z *= inv; s.w *= inv;
    ((float4*)(g_cat + (size_t)b*2*HW))[p4]      = m;   // maxmap (ch 0)
    ((float4*)(g_cat + (size_t)b*2*HW + HW))[p4] = s;   // avgmap (ch 1)
}

// ---------------- K4: offsets conv + deform conv + BN + sigmoid -> ws ----------------
// One row per block (128 threads). Conv neighborhood served from smem; offsets
// computed per tap on the fly (no off[18] array); bilinear gathers from L2.
__global__ __launch_bounds__(128, 8)
void k_deform(const float* __restrict__ off_w, const float* __restrict__ off_b,
              const float* __restrict__ dc_w,  const float* __restrict__ dc_b,
              const float* __restrict__ bn_gamma, const float* __restrict__ bn_beta,
              const float* __restrict__ bn_mean,  const float* __restrict__ bn_var) {
    __shared__ float s_ow[18*18];          // [ch][2*9] offset-conv weights
    __shared__ float s_ob[18], s_dw[18];
    __shared__ float t0[3][W], t1[3][W];   // 3 rows of maxmap / avgmap

    int b = blockIdx.x >> 7;
    int i = blockIdx.x & (H - 1);
    int j = threadIdx.x;

    // stage weights
    for (int t = threadIdx.x; t < 18*18; t += 128) s_ow[t] = off_w[t];
    if (threadIdx.x < 18) {
        s_ob[threadIdx.x] = off_b[threadIdx.x];
        s_dw[threadIdx.x] = dc_w[threadIdx.x];       // [ci*9 + k]
    }

    const float* c0 = g_cat + (size_t)b*2*HW;        // maxmap
    const float* c1 = c0 + HW;                       // avgmap

    // stage 3 rows (zero rows for OOB)
    #pragma unroll
    for (int r = 0; r < 3; r++) {
        int yy = i + r - 1;
        bool ok = (yy >= 0) & (yy < H);
        int idx = yy*W + j;
        t0[r][j] = ok ? c0[idx] : 0.f;
        t1[r][j] = ok ? c1[idx] : 0.f;
    }
    __syncthreads();

    // 3x3 neighborhood from smem (x boundary -> 0)
    float n0[9], n1[9];
    #pragma unroll
    for (int u = 0; u < 3; u++) {
        #pragma unroll
        for (int v = 0; v < 3; v++) {
            int xx = j + v - 1;
            bool ok = (xx >= 0) & (xx < W);
            int xc = min(max(xx, 0), W-1);
            n0[u*3+v] = ok ? t0[u][xc] : 0.f;
            n1[u*3+v] = ok ? t1[u][xc] : 0.f;
        }
    }

    float acc = __ldg(dc_b);
    const float fi = (float)i, fj = (float)j;

    #pragma unroll
    for (int k = 0; k < 9; k++) {
        // offset channels 2k (dy) and 2k+1 (dx), computed on the fly
        float oy = s_ob[2*k], ox = s_ob[2*k + 1];
        const float* wy_ = &s_ow[(2*k)*18];
        const float* wx_ = &s_ow[(2*k+1)*18];
        #pragma unroll
        for (int q = 0; q < 9; q++) {
            oy = fmaf(wy_[q],   n0[q], oy);
            oy = fmaf(wy_[9+q], n1[q], oy);
            ox = fmaf(wx_[q],   n0[q], ox);
            ox = fmaf(wx_[9+q], n1[q], ox);
        }
        float py = fi + (float)(k/3 - 1) + oy;
        float px = fj + (float)(k%3 - 1) + ox;
        float y0 = floorf(py), x0 = floorf(px);
        float wy = py - y0, wx = px - x0;
        int y0i = (int)y0, x0i = (int)x0;

        float s0 = 0.f, s1 = 0.f;
        #pragma unroll
        for (int dy = 0; dy < 2; dy++) {
            #pragma unroll
            for (int dx = 0; dx < 2; dx++) {
                int yi = y0i + dy, xi = x0i + dx;
                bool ok = (yi >= 0) & (yi < H) & (xi >= 0) & (xi < W);
                int yc = min(max(yi, 0), H-1);
                int xc = min(max(xi, 0), W-1);
                int idx = yc*W + xc;
                float wgt = (dy ? wy : 1.f - wy) * (dx ? wx : 1.f - wx);
                if (ok) {
                    s0 = fmaf(__ldg(&c0[idx]), wgt, s0);
                    s1 = fmaf(__ldg(&c1[idx]), wgt, s1);
                }
            }
        }
        acc = fmaf(s0, s_dw[k], acc);
        acc = fmaf(s1, s_dw[9 + k], acc);
    }

    float inv = __ldg(bn_gamma) * rsqrtf(__ldg(bn_var) + 1e-5f);
    float d = (acc - __ldg(bn_mean)) * inv + __ldg(bn_beta);
    g_ws[b*HW + i*W + j] = 1.f / (1.f + __expf(-d));
}

// ---------------- K5: out = x * (1 + wch*ws) ----------------
__global__ __launch_bounds__(256) void k_final(const float* __restrict__ x, float* __restrict__ out) {
    size_t i4 = (size_t)blockIdx.x * blockDim.x + threadIdx.x;  // float4 index
    size_t e  = i4 << 2;
    int b  = (int)(e >> 22);            // C*HW = 2^22
    int c  = (int)(e >> 14) & (C - 1);
    int hw = (int)e & (HW - 1);
    float w = g_wch[b*C + c];
    float4 xv  = ((const float4*)x)[i4];
    float4 wsv = __ldg((const float4*)(g_ws + (size_t)b*HW + hw));
    float4 o;
    o.x = xv.x * fmaf(w, wsv.x, 1.f);
    o.y = xv.y * fmaf(w, wsv.y, 1.f);
    o.z = xv.z * fmaf(w, wsv.z, 1.f);
    o.w = xv.w * fmaf(w, wsv.w, 1.f);
    ((float4*)out)[i4] = o;
}

extern "C" void kernel_launch(void* const* d_in, const int* in_sizes, int n_in,
                              void* d_out, int out_size) {
    const float* x     = (const float*)d_in[0];
    const float* w1    = (const float*)d_in[1];
    const float* b1    = (const float*)d_in[2];
    const float* w2    = (const float*)d_in[3];
    const float* b2    = (const float*)d_in[4];
    const float* off_w = (const float*)d_in[5];
    const float* off_b = (const float*)d_in[6];
    const float* dc_w  = (const float*)d_in[7];
    const float* dc_b  = (const float*)d_in[8];
    const float* bng   = (const float*)d_in[9];
    const float* bnb   = (const float*)d_in[10];
    const float* bnm   = (const float*)d_in[11];
    const float* bnv   = (const float*)d_in[12];
    float* out = (float*)d_out;

    k_reduce_hw<<<B*C, 256>>>(x);
    k_mlp<<<B, C>>>(w1, b1, w2, b2);
    {
        dim3 grid(HW/(128*4), B);
        k_cat<<<grid, 128>>>(x);
    }
    k_deform<<<B*H, 128>>>(off_w, off_b, dc_w, dc_b, bng, bnb, bnm, bnv);
    k_final<<<(B*C*HW)/4/256, 256>>>(x, out);
}

// round 5
// speedup vs baseline: 1.0524x; 1.0524x over previous
#include <cuda_runtime.h>
#include <math.h>

#define B 16
#define C 256
#define H 128
#define W 128
#define HW (H*W)
#define R 16

typedef unsigned long long ull;

// Scratch (allocation-free: __device__ globals)
__device__ float  g_avg[B*C];
__device__ float  g_max[B*C];
__device__ float  g_wch[B*C];
__device__ float2 g_cat2[B*HW];   // interleaved (maxmap, avgmap) per pixel
__device__ float  g_ws[B*HW];

// ---- packed f32x2 helpers (sm_100+) ----
__device__ __forceinline__ ull pack2(float a, float b) {
    ull r; asm("mov.b64 %0, {%1, %2};" : "=l"(r) : "f"(a), "f"(b)); return r;
}
__device__ __forceinline__ float2 unpack2(ull v) {
    float2 r; asm("mov.b64 {%0, %1}, %2;" : "=f"(r.x), "=f"(r.y) : "l"(v)); return r;
}
__device__ __forceinline__ ull ffma2(ull a, ull b, ull c) {
    ull d; asm("fma.rn.f32x2 %0, %1, %2, %3;" : "=l"(d) : "l"(a), "l"(b), "l"(c)); return d;
}

// ---------------- K1: per-(b,c) mean & max over H,W ----------------
__global__ __launch_bounds__(256) void k_reduce_hw(const float* __restrict__ x) {
    int bc = blockIdx.x;
    const float4* xp = (const float4*)(x + (size_t)bc * HW);
    float s = 0.f, m = -INFINITY;
    #pragma unroll 4
    for (int i = threadIdx.x; i < HW/4; i += blockDim.x) {
        float4 v = xp[i];
        s += (v.x + v.y) + (v.z + v.w);
        m = fmaxf(m, fmaxf(fmaxf(v.x, v.y), fmaxf(v.z, v.w)));
    }
    #pragma unroll
    for (int o = 16; o; o >>= 1) {
        s += __shfl_xor_sync(0xffffffffu, s, o);
        m = fmaxf(m, __shfl_xor_sync(0xffffffffu, m, o));
    }
    __shared__ float ss[8], sm[8];
    int w = threadIdx.x >> 5, l = threadIdx.x & 31;
    if (l == 0) { ss[w] = s; sm[w] = m; }
    __syncthreads();
    if (threadIdx.x == 0) {
        for (int i = 1; i < 8; i++) { s += ss[i]; m = fmaxf(m, sm[i]); }
        g_avg[bc] = s * (1.f / HW);
        g_max[bc] = m;
    }
}

// ---------------- K2+K3 fused: MLP -> wch (in smem), then cat maps ----------------
__global__ __launch_bounds__(128) void k_cat(const float* __restrict__ x,
                                             const float* __restrict__ w1, const float* __restrict__ b1,
                                             const float* __restrict__ w2, const float* __restrict__ b2) {
    int b = blockIdx.y;
    int t = threadIdx.x;
    __shared__ float s_avg[C], s_mx[C], s_h[R], sw[C];
    s_avg[t]       = g_avg[b*C + t];
    s_avg[t + 128] = g_avg[b*C + t + 128];
    s_mx[t]        = g_max[b*C + t];
    s_mx[t + 128]  = g_max[b*C + t + 128];
    __syncthreads();
    if (t < R) {
        float ha = b1[t], hm = b1[t];
        #pragma unroll 8
        for (int c = 0; c < C; c++) {
            float w = __ldg(&w1[t*C + c]);
            ha = fmaf(w, s_avg[c], ha);
            hm = fmaf(w, s_mx[c],  hm);
        }
        s_h[t] = fmaxf(ha, 0.f) + fmaxf(hm, 0.f);
    }
    __syncthreads();
    #pragma unroll
    for (int cc = 0; cc < 2; cc++) {
        int c = t + cc*128;
        float o = 2.f * __ldg(&b2[c]);
        #pragma unroll
        for (int r = 0; r < R; r++) o = fmaf(__ldg(&w2[c*R + r]), s_h[r], o);
        float v = 1.f / (1.f + __expf(-o));
        sw[c] = v;
        if (blockIdx.x == 0) g_wch[b*C + c] = v;   // persist for K5
    }
    __syncthreads();

    int p4 = blockIdx.x * blockDim.x + threadIdx.x;   // float4 index within HW
    const float4* xb = (const float4*)(x + (size_t)b * C * HW);
    float4 s = make_float4(0.f, 0.f, 0.f, 0.f);
    float4 m = make_float4(-INFINITY, -INFINITY, -INFINITY, -INFINITY);
    #pragma unroll 8
    for (int c = 0; c < C; c++) {
        float4 v = __ldg(&xb[(size_t)c * (HW/4) + p4]);
        float w = sw[c];
        float a0 = w*v.x, a1 = w*v.y, a2 = w*v.z, a3 = w*v.w;
        s.x += a0; s.y += a1; s.z += a2; s.w += a3;
        m.x = fmaxf(m.x, a0); m.y = fmaxf(m.y, a1);
        m.z = fmaxf(m.z, a2); m.w = fmaxf(m.w, a3);
    }
    const float inv = 1.f / C;
    // interleaved store: 4 pixels -> 4 float2 -> 2 float4
    float4* dst = (float4*)(g_cat2 + (size_t)b*HW + (size_t)p4*4);
    dst[0] = make_float4(m.x, s.x*inv, m.y, s.y*inv);
    dst[1] = make_float4(m.z, s.z*inv, m.w, s.w*inv);
}

// ---------------- K4: offsets conv + deform conv + BN + sigmoid -> ws ----------------
// One row per 128-thread block. Offset conv done with packed f32x2 FMAs
// (paired dy/dx channels), bilinear with one LDG.64 + one FFMA2 per corner.
__global__ __launch_bounds__(128, 6)
void k_deform(const float* __restrict__ off_w, const float* __restrict__ off_b,
              const float* __restrict__ dc_w,  const float* __restrict__ dc_b,
              const float* __restrict__ bn_gamma, const float* __restrict__ bn_beta,
              const float* __restrict__ bn_mean,  const float* __restrict__ bn_var) {
    __shared__ ull   s_wp[9][18];     // [tap][q] = (w_dy[q], w_dx[q])
    __shared__ ull   s_obp[9];        // (off_b[2k], off_b[2k+1])
    __shared__ float s_dw[18];
    __shared__ float2 trow[3][W];     // 3 staged rows of (max,avg)

    int b = blockIdx.x >> 7;
    int i = blockIdx.x & (H - 1);
    int j = threadIdx.x;

    // stage packed weights
    for (int t = threadIdx.x; t < 162; t += 128) {
        int k = t / 18, q = t - k*18;
        s_wp[k][q] = pack2(off_w[(2*k)*18 + q], off_w[(2*k+1)*18 + q]);
    }
    if (threadIdx.x < 9)  s_obp[threadIdx.x] = pack2(off_b[2*threadIdx.x], off_b[2*threadIdx.x + 1]);
    if (threadIdx.x < 18) s_dw[threadIdx.x]  = dc_w[threadIdx.x];

    const float2* c2 = g_cat2 + (size_t)b*HW;

    #pragma unroll
    for (int r = 0; r < 3; r++) {
        int yy = i + r - 1;
        bool ok = (unsigned)yy < H;
        trow[r][j] = ok ? c2[yy*W + j] : make_float2(0.f, 0.f);
    }
    __syncthreads();

    // duplicated packed neighborhood: na (maxmap), nb (avgmap), q = u*3+v
    ull na[9], nb[9];
    #pragma unroll
    for (int u = 0; u < 3; u++) {
        #pragma unroll
        for (int v = 0; v < 3; v++) {
            int xx = j + v - 1;
            bool ok = (unsigned)xx < W;
            int xc = min(max(xx, 0), W-1);
            float2 val = trow[u][xc];
            float vx = ok ? val.x : 0.f;
            float vy = ok ? val.y : 0.f;
            na[u*3+v] = pack2(vx, vx);
            nb[u*3+v] = pack2(vy, vy);
        }
    }

    float acc = __ldg(dc_b);
    const float fi = (float)i, fj = (float)j;

    #pragma unroll
    for (int k = 0; k < 9; k++) {
        ull a2 = s_obp[k];
        #pragma unroll
        for (int q = 0; q < 9; q++) a2 = ffma2(s_wp[k][q],     na[q], a2);
        #pragma unroll
        for (int q = 0; q < 9; q++) a2 = ffma2(s_wp[k][9 + q], nb[q], a2);
        float2 o = unpack2(a2);           // o.x = dy, o.y = dx

        float py = fi + (float)(k/3 - 1) + o.x;
        float px = fj + (float)(k%3 - 1) + o.y;
        float y0f = floorf(py), x0f = floorf(px);
        float wy = py - y0f, wx = px - x0f;
        float omwy = 1.f - wy, omwx = 1.f - wx;
        int y0 = (int)y0f, x0 = (int)x0f;

        ull sacc = 0ull;
        #pragma unroll
        for (int dy = 0; dy < 2; dy++) {
            #pragma unroll
            for (int dx = 0; dx < 2; dx++) {
                int yi = y0 + dy, xi = x0 + dx;
                bool ok = ((unsigned)yi < H) & ((unsigned)xi < W);
                float wgt = (dy ? wy : omwy) * (dx ? wx : omwx);
                wgt = ok ? wgt : 0.f;
                int idx = min(max(yi, 0), H-1) * W + min(max(xi, 0), W-1);
                ull v = *(const ull*)(c2 + idx);     // (max, avg) one LDG.64
                sacc = ffma2(v, pack2(wgt, wgt), sacc);
            }
        }
        float2 sv = unpack2(sacc);
        acc = fmaf(sv.x, s_dw[k],     acc);
        acc = fmaf(sv.y, s_dw[9 + k], acc);
    }

    float inv = __ldg(bn_gamma) * rsqrtf(__ldg(bn_var) + 1e-5f);
    float d = (acc - __ldg(bn_mean)) * inv + __ldg(bn_beta);
    g_ws[b*HW + i*W + j] = 1.f / (1.f + __expf(-d));
}

// ---------------- K5: out = x * (1 + wch*ws) ----------------
__global__ __launch_bounds__(256) void k_final(const float* __restrict__ x, float* __restrict__ out) {
    size_t i4 = (size_t)blockIdx.x * blockDim.x + threadIdx.x;  // float4 index
    size_t e  = i4 << 2;
    int b  = (int)(e >> 22);            // C*HW = 2^22
    int c  = (int)(e >> 14) & (C - 1);
    int hw = (int)e & (HW - 1);
    float w = g_wch[b*C + c];
    float4 xv  = ((const float4*)x)[i4];
    float4 wsv = __ldg((const float4*)(g_ws + (size_t)b*HW + hw));
    float4 o;
    o.x = xv.x * fmaf(w, wsv.x, 1.f);
    o.y = xv.y * fmaf(w, wsv.y, 1.f);
    o.z = xv.z * fmaf(w, wsv.z, 1.f);
    o.w = xv.w * fmaf(w, wsv.w, 1.f);
    ((float4*)out)[i4] = o;
}

extern "C" void kernel_launch(void* const* d_in, const int* in_sizes, int n_in,
                              void* d_out, int out_size) {
    const float* x     = (const float*)d_in[0];
    const float* w1    = (const float*)d_in[1];
    const float* b1    = (const float*)d_in[2];
    const float* w2    = (const float*)d_in[3];
    const float* b2    = (const float*)d_in[4];
    const float* off_w = (const float*)d_in[5];
    const float* off_b = (const float*)d_in[6];
    const float* dc_w  = (const float*)d_in[7];
    const float* dc_b  = (const float*)d_in[8];
    const float* bng   = (const float*)d_in[9];
    const float* bnb   = (const float*)d_in[10];
    const float* bnm   = (const float*)d_in[11];
    const float* bnv   = (const float*)d_in[12];
    float* out = (float*)d_out;

    k_reduce_hw<<<B*C, 256>>>(x);
    {
        dim3 grid(HW/(128*4), B);
        k_cat<<<grid, 128>>>(x, w1, b1, w2, b2);
    }
    k_deform<<<B*H, 128>>>(off_w, off_b, dc_w, dc_b, bng, bnb, bnm, bnv);
    k_final<<<(B*C*HW)/4/256, 256>>>(x, out);
}

// round 6
// speedup vs baseline: 1.0938x; 1.0394x over previous
#include <cuda_runtime.h>
#include <math.h>

#define B 16
#define C 256
#define H 128
#define W 128
#define HW (H*W)
#define R 16

typedef unsigned long long ull;

// Scratch (allocation-free: __device__ globals)
__device__ float  g_avg[B*C];
__device__ float  g_max[B*C];
__device__ float  g_wch[B*C];
__device__ float2 g_cat2[B*HW];   // interleaved (maxmap, avgmap) per pixel
__device__ float  g_ws[B*HW];

// ---- packed f32x2 helpers (sm_100+) ----
__device__ __forceinline__ ull pack2(float a, float b) {
    ull r; asm("mov.b64 %0, {%1, %2};" : "=l"(r) : "f"(a), "f"(b)); return r;
}
__device__ __forceinline__ float2 unpack2(ull v) {
    float2 r; asm("mov.b64 {%0, %1}, %2;" : "=f"(r.x), "=f"(r.y) : "l"(v)); return r;
}
__device__ __forceinline__ ull ffma2(ull a, ull b, ull c) {
    ull d; asm("fma.rn.f32x2 %0, %1, %2, %3;" : "=l"(d) : "l"(a), "l"(b), "l"(c)); return d;
}
// streaming (evict-first) float4 load/store
__device__ __forceinline__ float4 ldcs4(const float4* p) {
    float4 v;
    asm("ld.global.cs.v4.f32 {%0,%1,%2,%3}, [%4];"
        : "=f"(v.x), "=f"(v.y), "=f"(v.z), "=f"(v.w) : "l"(p));
    return v;
}
__device__ __forceinline__ void stcs4(float4* p, float4 v) {
    asm volatile("st.global.cs.v4.f32 [%0], {%1,%2,%3,%4};"
                 :: "l"(p), "f"(v.x), "f"(v.y), "f"(v.z), "f"(v.w));
}

// ---------------- K1: per-(b,c) mean & max over H,W ----------------
__global__ __launch_bounds__(256) void k_reduce_hw(const float* __restrict__ x) {
    int bc = blockIdx.x;
    const float4* xp = (const float4*)(x + (size_t)bc * HW);
    float s = 0.f, m = -INFINITY;
    #pragma unroll 8
    for (int i = threadIdx.x; i < HW/4; i += blockDim.x) {
        float4 v = ldcs4(&xp[i]);
        s += (v.x + v.y) + (v.z + v.w);
        m = fmaxf(m, fmaxf(fmaxf(v.x, v.y), fmaxf(v.z, v.w)));
    }
    #pragma unroll
    for (int o = 16; o; o >>= 1) {
        s += __shfl_xor_sync(0xffffffffu, s, o);
        m = fmaxf(m, __shfl_xor_sync(0xffffffffu, m, o));
    }
    __shared__ float ss[8], sm[8];
    int w = threadIdx.x >> 5, l = threadIdx.x & 31;
    if (l == 0) { ss[w] = s; sm[w] = m; }
    __syncthreads();
    if (threadIdx.x == 0) {
        for (int i = 1; i < 8; i++) { s += ss[i]; m = fmaxf(m, sm[i]); }
        g_avg[bc] = s * (1.f / HW);
        g_max[bc] = m;
    }
}

// ---------------- K2+K3 fused: MLP -> wch (in smem), then cat maps ----------------
__global__ __launch_bounds__(128) void k_cat(const float* __restrict__ x,
                                             const float* __restrict__ w1, const float* __restrict__ b1,
                                             const float* __restrict__ w2, const float* __restrict__ b2) {
    int b = blockIdx.y;
    int t = threadIdx.x;
    __shared__ float s_avg[C], s_mx[C], s_h[R], sw[C];
    s_avg[t]       = g_avg[b*C + t];
    s_avg[t + 128] = g_avg[b*C + t + 128];
    s_mx[t]        = g_max[b*C + t];
    s_mx[t + 128]  = g_max[b*C + t + 128];
    __syncthreads();
    if (t < R) {
        float ha = b1[t], hm = b1[t];
        #pragma unroll 8
        for (int c = 0; c < C; c++) {
            float w = __ldg(&w1[t*C + c]);
            ha = fmaf(w, s_avg[c], ha);
            hm = fmaf(w, s_mx[c],  hm);
        }
        s_h[t] = fmaxf(ha, 0.f) + fmaxf(hm, 0.f);
    }
    __syncthreads();
    #pragma unroll
    for (int cc = 0; cc < 2; cc++) {
        int c = t + cc*128;
        float o = 2.f * __ldg(&b2[c]);
        #pragma unroll
        for (int r = 0; r < R; r++) o = fmaf(__ldg(&w2[c*R + r]), s_h[r], o);
        float v = 1.f / (1.f + __expf(-o));
        sw[c] = v;
        if (blockIdx.x == 0) g_wch[b*C + c] = v;   // persist for K5
    }
    __syncthreads();

    int p4 = blockIdx.x * blockDim.x + threadIdx.x;   // float4 index within HW
    const float4* xb = (const float4*)(x + (size_t)b * C * HW);
    float4 s = make_float4(0.f, 0.f, 0.f, 0.f);
    float4 m = make_float4(-INFINITY, -INFINITY, -INFINITY, -INFINITY);
    #pragma unroll 8
    for (int c = 0; c < C; c++) {
        float4 v = ldcs4(&xb[(size_t)c * (HW/4) + p4]);
        float w = sw[c];
        float a0 = w*v.x, a1 = w*v.y, a2 = w*v.z, a3 = w*v.w;
        s.x += a0; s.y += a1; s.z += a2; s.w += a3;
        m.x = fmaxf(m.x, a0); m.y = fmaxf(m.y, a1);
        m.z = fmaxf(m.z, a2); m.w = fmaxf(m.w, a3);
    }
    const float inv = 1.f / C;
    float4* dst = (float4*)(g_cat2 + (size_t)b*HW + (size_t)p4*4);
    dst[0] = make_float4(m.x, s.x*inv, m.y, s.y*inv);
    dst[1] = make_float4(m.z, s.z*inv, m.w, s.w*inv);
}

// ---------------- K4: offsets conv + deform conv + BN + sigmoid -> ws ----------------
__global__ __launch_bounds__(128, 6)
void k_deform(const float* __restrict__ off_w, const float* __restrict__ off_b,
              const float* __restrict__ dc_w,  const float* __restrict__ dc_b,
              const float* __restrict__ bn_gamma, const float* __restrict__ bn_beta,
              const float* __restrict__ bn_mean,  const float* __restrict__ bn_var) {
    __shared__ ull   s_wp[9][18];     // [tap][q] = (w_dy[q], w_dx[q])
    __shared__ ull   s_obp[9];        // (off_b[2k], off_b[2k+1])
    __shared__ float s_dw[18];
    __shared__ float2 trow[3][W];     // 3 staged rows of (max,avg)

    int b = blockIdx.x >> 7;
    int i = blockIdx.x & (H - 1);
    int j = threadIdx.x;

    for (int t = threadIdx.x; t < 162; t += 128) {
        int k = t / 18, q = t - k*18;
        s_wp[k][q] = pack2(off_w[(2*k)*18 + q], off_w[(2*k+1)*18 + q]);
    }
    if (threadIdx.x < 9)  s_obp[threadIdx.x] = pack2(off_b[2*threadIdx.x], off_b[2*threadIdx.x + 1]);
    if (threadIdx.x < 18) s_dw[threadIdx.x]  = dc_w[threadIdx.x];

    const float2* c2 = g_cat2 + (size_t)b*HW;

    #pragma unroll
    for (int r = 0; r < 3; r++) {
        int yy = i + r - 1;
        bool ok = (unsigned)yy < H;
        trow[r][j] = ok ? c2[yy*W + j] : make_float2(0.f, 0.f);
    }
    __syncthreads();

    ull na[9], nb[9];
    #pragma unroll
    for (int u = 0; u < 3; u++) {
        #pragma unroll
        for (int v = 0; v < 3; v++) {
            int xx = j + v - 1;
            bool ok = (unsigned)xx < W;
            int xc = min(max(xx, 0), W-1);
            float2 val = trow[u][xc];
            float vx = ok ? val.x : 0.f;
            float vy = ok ? val.y : 0.f;
            na[u*3+v] = pack2(vx, vx);
            nb[u*3+v] = pack2(vy, vy);
        }
    }

    float acc = __ldg(dc_b);
    const float fi = (float)i, fj = (float)j;

    #pragma unroll
    for (int k = 0; k < 9; k++) {
        ull a2 = s_obp[k];
        #pragma unroll
        for (int q = 0; q < 9; q++) a2 = ffma2(s_wp[k][q],     na[q], a2);
        #pragma unroll
        for (int q = 0; q < 9; q++) a2 = ffma2(s_wp[k][9 + q], nb[q], a2);
        float2 o = unpack2(a2);           // o.x = dy, o.y = dx

        float py = fi + (float)(k/3 - 1) + o.x;
        float px = fj + (float)(k%3 - 1) + o.y;
        float y0f = floorf(py), x0f = floorf(px);
        float wy = py - y0f, wx = px - x0f;
        float omwy = 1.f - wy, omwx = 1.f - wx;
        int y0 = (int)y0f, x0 = (int)x0f;

        ull sacc = 0ull;
        #pragma unroll
        for (int dy = 0; dy < 2; dy++) {
            #pragma unroll
            for (int dx = 0; dx < 2; dx++) {
                int yi = y0 + dy, xi = x0 + dx;
                bool ok = ((unsigned)yi < H) & ((unsigned)xi < W);
                float wgt = (dy ? wy : omwy) * (dx ? wx : omwx);
                wgt = ok ? wgt : 0.f;
                int idx = min(max(yi, 0), H-1) * W + min(max(xi, 0), W-1);
                ull v = *(const ull*)(c2 + idx);
                sacc = ffma2(v, pack2(wgt, wgt), sacc);
            }
        }
        float2 sv = unpack2(sacc);
        acc = fmaf(sv.x, s_dw[k],     acc);
        acc = fmaf(sv.y, s_dw[9 + k], acc);
    }

    float inv = __ldg(bn_gamma) * rsqrtf(__ldg(bn_var) + 1e-5f);
    float d = (acc - __ldg(bn_mean)) * inv + __ldg(bn_beta);
    g_ws[b*HW + i*W + j] = 1.f / (1.f + __expf(-d));
}

// ---------------- K5: out = x * (1 + wch*ws) ----------------
// 2 float4 per thread (block covers 512 consecutive float4 = one (b,c) slice),
// streaming loads/stores for x/out, L2-cached ws.
__global__ __launch_bounds__(256) void k_final(const float* __restrict__ x, float* __restrict__ out) {
    size_t base = (size_t)blockIdx.x * 512 + threadIdx.x;   // float4 index
    size_t e    = base << 2;
    int b  = (int)(e >> 22);            // C*HW = 2^22
    int c  = (int)(e >> 14) & (C - 1);  // uniform across the block
    float w = __ldg(&g_wch[b*C + c]);

    int hw0 = (int)e & (HW - 1);
    const float4* wsp = (const float4*)(g_ws + (size_t)b*HW);

    float4 xv0  = ldcs4((const float4*)x + base);
    float4 xv1  = ldcs4((const float4*)x + base + 256);
    float4 ws0  = __ldg(&wsp[hw0 >> 2]);
    float4 ws1  = __ldg(&wsp[(hw0 + 1024) >> 2]);

    float4 o0, o1;
    o0.x = xv0.x * fmaf(w, ws0.x, 1.f);
    o0.y = xv0.y * fmaf(w, ws0.y, 1.f);
    o0.z = xv0.z * fmaf(w, ws0.z, 1.f);
    o0.w = xv0.w * fmaf(w, ws0.w, 1.f);
    o1.x = xv1.x * fmaf(w, ws1.x, 1.f);
    o1.y = xv1.y * fmaf(w, ws1.y, 1.f);
    o1.z = xv1.z * fmaf(w, ws1.z, 1.f);
    o1.w = xv1.w * fmaf(w, ws1.w, 1.f);
    stcs4((float4*)out + base,       o0);
    stcs4((float4*)out + base + 256, o1);
}

extern "C" void kernel_launch(void* const* d_in, const int* in_sizes, int n_in,
                              void* d_out, int out_size) {
    const float* x     = (const float*)d_in[0];
    const float* w1    = (const float*)d_in[1];
    const float* b1    = (const float*)d_in[2];
    const float* w2    = (const float*)d_in[3];
    const float* b2    = (const float*)d_in[4];
    const float* off_w = (const float*)d_in[5];
    const float* off_b = (const float*)d_in[6];
    const float* dc_w  = (const float*)d_in[7];
    const float* dc_b  = (const float*)d_in[8];
    const float* bng   = (const float*)d_in[9];
    const float* bnb   = (const float*)d_in[10];
    const float* bnm   = (const float*)d_in[11];
    const float* bnv   = (const float*)d_in[12];
    float* out = (float*)d_out;

    k_reduce_hw<<<B*C, 256>>>(x);
    {
        dim3 grid(HW/(128*4), B);
        k_cat<<<grid, 128>>>(x, w1, b1, w2, b2);
    }
    k_deform<<<B*H, 128>>>(off_w, off_b, dc_w, dc_b, bng, bnb, bnm, bnv);
    k_final<<<(B*C*HW)/4/512, 256>>>(x, out);
}

// round 8
// speedup vs baseline: 1.1501x; 1.0515x over previous
#include <cuda_runtime.h>
#include <math.h>

#define B 16
#define C 256
#define H 128
#define W 128
#define HW (H*W)
#define R 16
#define CSPLIT 4
#define CCHUNK (C/CSPLIT)   // 64

typedef unsigned long long ull;

// Scratch (allocation-free: __device__ globals)
__device__ float  g_avg[B*C];
__device__ float  g_max[B*C];
__device__ float  g_wch[B*C];
__device__ float2 g_part[CSPLIT][B*HW]; // partial (max,sum) per channel-chunk
__device__ float2 g_cat2[B*HW];         // interleaved (maxmap, avgmap) per pixel
__device__ float  g_ws[B*HW];

// ---- packed f32x2 helpers (sm_100+) ----
__device__ __forceinline__ ull pack2(float a, float b) {
    ull r; asm("mov.b64 %0, {%1, %2};" : "=l"(r) : "f"(a), "f"(b)); return r;
}
__device__ __forceinline__ float2 unpack2(ull v) {
    float2 r; asm("mov.b64 {%0, %1}, %2;" : "=f"(r.x), "=f"(r.y) : "l"(v)); return r;
}
__device__ __forceinline__ ull ffma2(ull a, ull b, ull c) {
    ull d; asm("fma.rn.f32x2 %0, %1, %2, %3;" : "=l"(d) : "l"(a), "l"(b), "l"(c)); return d;
}
// streaming (evict-first) float4 load/store
__device__ __forceinline__ float4 ldcs4(const float4* p) {
    float4 v;
    asm("ld.global.cs.v4.f32 {%0,%1,%2,%3}, [%4];"
        : "=f"(v.x), "=f"(v.y), "=f"(v.z), "=f"(v.w) : "l"(p));
    return v;
}
__device__ __forceinline__ void stcs4(float4* p, float4 v) {
    asm volatile("st.global.cs.v4.f32 [%0], {%1,%2,%3,%4};"
                 :: "l"(p), "f"(v.x), "f"(v.y), "f"(v.z), "f"(v.w));
}

// ---------------- K1: per-(b,c) mean & max over H,W ----------------
__global__ __launch_bounds__(256) void k_reduce_hw(const float* __restrict__ x) {
    int bc = blockIdx.x;
    const float4* xp = (const float4*)(x + (size_t)bc * HW);
    float s0 = 0.f, s1 = 0.f, m0 = -INFINITY, m1 = -INFINITY;
    #pragma unroll 4
    for (int i = threadIdx.x; i < HW/8; i += blockDim.x) {
        float4 v = ldcs4(&xp[i]);
        float4 u = ldcs4(&xp[i + HW/8]);
        s0 += (v.x + v.y) + (v.z + v.w);
        s1 += (u.x + u.y) + (u.z + u.w);
        m0 = fmaxf(m0, fmaxf(fmaxf(v.x, v.y), fmaxf(v.z, v.w)));
        m1 = fmaxf(m1, fmaxf(fmaxf(u.x, u.y), fmaxf(u.z, u.w)));
    }
    float s = s0 + s1, m = fmaxf(m0, m1);
    #pragma unroll
    for (int o = 16; o; o >>= 1) {
        s += __shfl_xor_sync(0xffffffffu, s, o);
        m = fmaxf(m, __shfl_xor_sync(0xffffffffu, m, o));
    }
    __shared__ float ss[8], sm[8];
    int w = threadIdx.x >> 5, l = threadIdx.x & 31;
    if (l == 0) { ss[w] = s; sm[w] = m; }
    __syncthreads();
    if (threadIdx.x == 0) {
        for (int i = 1; i < 8; i++) { s += ss[i]; m = fmaxf(m, sm[i]); }
        g_avg[bc] = s * (1.f / HW);
        g_max[bc] = m;
    }
}

// ---------------- K2+K3: MLP -> wch, then partial cat maps over 64 channels ----------------
// grid (HW/4/256, B, CSPLIT), block 256
__global__ __launch_bounds__(256) void k_cat(const float* __restrict__ x,
                                             const float* __restrict__ w1, const float* __restrict__ b1,
                                             const float* __restrict__ w2, const float* __restrict__ b2) {
    int b  = blockIdx.y;
    int cz = blockIdx.z;
    int t  = threadIdx.x;
    __shared__ float s_avg[C], s_mx[C], s_h[R], sw[CCHUNK];
    s_avg[t] = g_avg[b*C + t];
    s_mx[t]  = g_max[b*C + t];
    __syncthreads();
    if (t < R) {
        float ha = b1[t], hm = b1[t];
        #pragma unroll 8
        for (int c = 0; c < C; c++) {
            float w = __ldg(&w1[t*C + c]);
            ha = fmaf(w, s_avg[c], ha);
            hm = fmaf(w, s_mx[c],  hm);
        }
        s_h[t] = fmaxf(ha, 0.f) + fmaxf(hm, 0.f);
    }
    __syncthreads();
    if (t < CCHUNK) {
        int c = cz*CCHUNK + t;
        float o = 2.f * __ldg(&b2[c]);
        #pragma unroll
        for (int r = 0; r < R; r++) o = fmaf(__ldg(&w2[c*R + r]), s_h[r], o);
        float v = 1.f / (1.f + __expf(-o));
        sw[t] = v;
        if (blockIdx.x == 0) g_wch[b*C + c] = v;   // one writer per channel
    }
    __syncthreads();

    int p4 = blockIdx.x * blockDim.x + threadIdx.x;   // float4 index within HW
    const float4* xb = (const float4*)(x + (size_t)b * C * HW + (size_t)cz*CCHUNK*HW);
    float4 s = make_float4(0.f, 0.f, 0.f, 0.f);
    float4 m = make_float4(-INFINITY, -INFINITY, -INFINITY, -INFINITY);
    #pragma unroll 8
    for (int c = 0; c < CCHUNK; c++) {
        float4 v = ldcs4(&xb[(size_t)c * (HW/4) + p4]);
        float w = sw[c];
        float a0 = w*v.x, a1 = w*v.y, a2 = w*v.z, a3 = w*v.w;
        s.x += a0; s.y += a1; s.z += a2; s.w += a3;
        m.x = fmaxf(m.x, a0); m.y = fmaxf(m.y, a1);
        m.z = fmaxf(m.z, a2); m.w = fmaxf(m.w, a3);
    }
    float4* dst = (float4*)(g_part[cz] + (size_t)b*HW + (size_t)p4*4);
    dst[0] = make_float4(m.x, s.x, m.y, s.y);
    dst[1] = make_float4(m.z, s.z, m.w, s.w);
}

// ---------------- K3b: combine the CSPLIT partials -> g_cat2 ----------------
// one thread per 2 pixels (float4 = 2 float2)
__global__ __launch_bounds__(256) void k_combine() {
    int i = blockIdx.x * blockDim.x + threadIdx.x;   // 0 .. B*HW/2-1
    float4 a = ((const float4*)g_part[0])[i];
    float4 c = ((const float4*)g_part[1])[i];
    float4 d = ((const float4*)g_part[2])[i];
    float4 e = ((const float4*)g_part[3])[i];
    const float inv = 1.f / C;
    float4 o;
    o.x = fmaxf(fmaxf(a.x, c.x), fmaxf(d.x, e.x));
    o.y = ((a.y + c.y) + (d.y + e.y)) * inv;
    o.z = fmaxf(fmaxf(a.z, c.z), fmaxf(d.z, e.z));
    o.w = ((a.w + c.w) + (d.w + e.w)) * inv;
    ((float4*)g_cat2)[i] = o;
}

// ---------------- K4: offsets conv + deform conv + BN + sigmoid -> ws ----------------
__global__ __launch_bounds__(128, 6)
void k_deform(const float* __restrict__ off_w, const float* __restrict__ off_b,
              const float* __restrict__ dc_w,  const float* __restrict__ dc_b,
              const float* __restrict__ bn_gamma, const float* __restrict__ bn_beta,
              const float* __restrict__ bn_mean,  const float* __restrict__ bn_var) {
    __shared__ ull   s_wp[9][18];     // [tap][q] = (w_dy[q], w_dx[q])
    __shared__ ull   s_obp[9];        // (off_b[2k], off_b[2k+1])
    __shared__ float s_dw[18];
    __shared__ float2 trow[3][W];     // 3 staged rows of (max,avg)

    int b = blockIdx.x >> 7;
    int i = blockIdx.x & (H - 1);
    int j = threadIdx.x;

    for (int t = threadIdx.x; t < 162; t += 128) {
        int k = t / 18, q = t - k*18;
        s_wp[k][q] = pack2(off_w[(2*k)*18 + q], off_w[(2*k+1)*18 + q]);
    }
    if (threadIdx.x < 9)  s_obp[threadIdx.x] = pack2(off_b[2*threadIdx.x], off_b[2*threadIdx.x + 1]);
    if (threadIdx.x < 18) s_dw[threadIdx.x]  = dc_w[threadIdx.x];

    const float2* c2 = g_cat2 + (size_t)b*HW;

    #pragma unroll
    for (int r = 0; r < 3; r++) {
        int yy = i + r - 1;
        bool ok = (unsigned)yy < H;
        trow[r][j] = ok ? c2[yy*W + j] : make_float2(0.f, 0.f);
    }
    __syncthreads();

    ull na[9], nb[9];
    #pragma unroll
    for (int u = 0; u < 3; u++) {
        #pragma unroll
        for (int v = 0; v < 3; v++) {
            int xx = j + v - 1;
            bool ok = (unsigned)xx < W;
            int xc = min(max(xx, 0), W-1);
            float2 val = trow[u][xc];
            float vx = ok ? val.x : 0.f;
            float vy = ok ? val.y : 0.f;
            na[u*3+v] = pack2(vx, vx);
            nb[u*3+v] = pack2(vy, vy);
        }
    }

    float acc = __ldg(dc_b);
    const float fi = (float)i, fj = (float)j;

    #pragma unroll
    for (int k = 0; k < 9; k++) {
        ull a2 = s_obp[k];
        #pragma unroll
        for (int q = 0; q < 9; q++) a2 = ffma2(s_wp[k][q],     na[q], a2);
        #pragma unroll
        for (int q = 0; q < 9; q++) a2 = ffma2(s_wp[k][9 + q], nb[q], a2);
        float2 o = unpack2(a2);           // o.x = dy, o.y = dx

        float py = fi + (float)(k/3 - 1) + o.x;
        float px = fj + (float)(k%3 - 1) + o.y;
        float y0f = floorf(py), x0f = floorf(px);
        float wy = py - y0f, wx = px - x0f;
        float omwy = 1.f - wy, omwx = 1.f - wx;
        int y0 = (int)y0f, x0 = (int)x0f;

        ull sacc = 0ull;
        #pragma unroll
        for (int dy = 0; dy < 2; dy++) {
            #pragma unroll
            for (int dx = 0; dx < 2; dx++) {
                int yi = y0 + dy, xi = x0 + dx;
                bool ok = ((unsigned)yi < H) & ((unsigned)xi < W);
                float wgt = (dy ? wy : omwy) * (dx ? wx : omwx);
                wgt = ok ? wgt : 0.f;
                int idx = min(max(yi, 0), H-1) * W + min(max(xi, 0), W-1);
                ull v = *(const ull*)(c2 + idx);
                sacc = ffma2(v, pack2(wgt, wgt), sacc);
            }
        }
        float2 sv = unpack2(sacc);
        acc = fmaf(sv.x, s_dw[k],     acc);
        acc = fmaf(sv.y, s_dw[9 + k], acc);
    }

    float inv = __ldg(bn_gamma) * rsqrtf(__ldg(bn_var) + 1e-5f);
    float d = (acc - __ldg(bn_mean)) * inv + __ldg(bn_beta);
    g_ws[b*HW + i*W + j] = 1.f / (1.f + __expf(-d));
}

// ---------------- K5: out = x * (1 + wch*ws) ----------------
__global__ __launch_bounds__(256) void k_final(const float* __restrict__ x, float* __restrict__ out) {
    size_t base = (size_t)blockIdx.x * 512 + threadIdx.x;   // float4 index
    size_t e    = base << 2;
    int b  = (int)(e >> 22);            // C*HW = 2^22
    int c  = (int)(e >> 14) & (C - 1);  // uniform across the block
    float w = __ldg(&g_wch[b*C + c]);

    int hw0 = (int)e & (HW - 1);
    const float4* wsp = (const float4*)(g_ws + (size_t)b*HW);

    float4 xv0  = ldcs4((const float4*)x + base);
    float4 xv1  = ldcs4((const float4*)x + base + 256);
    float4 ws0  = __ldg(&wsp[hw0 >> 2]);
    float4 ws1  = __ldg(&wsp[(hw0 + 1024) >> 2]);

    float4 o0, o1;
    o0.x = xv0.x * fmaf(w, ws0.x, 1.f);
    o0.y = xv0.y * fmaf(w, ws0.y, 1.f);
    o0.z = xv0.z * fmaf(w, ws0.z, 1.f);
    o0.w = xv0.w * fmaf(w, ws0.w, 1.f);
    o1.x = xv1.x * fmaf(w, ws1.x, 1.f);
    o1.y = xv1.y * fmaf(w, ws1.y, 1.f);
    o1.z = xv1.z * fmaf(w, ws1.z, 1.f);
    o1.w = xv1.w * fmaf(w, ws1.w, 1.f);
    stcs4((float4*)out + base,       o0);
    stcs4((float4*)out + base + 256, o1);
}

extern "C" void kernel_launch(void* const* d_in, const int* in_sizes, int n_in,
                              void* d_out, int out_size) {
    const float* x     = (const float*)d_in[0];
    const float* w1    = (const float*)d_in[1];
    const float* b1    = (const float*)d_in[2];
    const float* w2    = (const float*)d_in[3];
    const float* b2    = (const float*)d_in[4];
    const float* off_w = (const float*)d_in[5];
    const float* off_b = (const float*)d_in[6];
    const float* dc_w  = (const float*)d_in[7];
    const float* dc_b  = (const float*)d_in[8];
    const float* bng   = (const float*)d_in[9];
    const float* bnb   = (const float*)d_in[10];
    const float* bnm   = (const float*)d_in[11];
    const float* bnv   = (const float*)d_in[12];
    float* out = (float*)d_out;

    k_reduce_hw<<<B*C, 256>>>(x);
    {
        dim3 grid(HW/4/256, B, CSPLIT);
        k_cat<<<grid, 256>>>(x, w1, b1, w2, b2);
    }
    k_combine<<<(B*HW/2)/256, 256>>>();
    k_deform<<<B*H, 128>>>(off_w, off_b, dc_w, dc_b, bng, bnb, bnm, bnv);
    k_final<<<(B*C*HW)/4/512, 256>>>(x, out);
}

// round 9
// speedup vs baseline: 1.1768x; 1.0231x over previous
#include <cuda_runtime.h>
#include <math.h>

#define B 16
#define C 256
#define H 128
#define W 128
#define HW (H*W)
#define R 16
#define CSPLIT 4
#define CCHUNK (C/CSPLIT)   // 64

typedef unsigned long long ull;

// Scratch (allocation-free: __device__ globals)
__device__ float  g_avg[B*C];
__device__ float  g_max[B*C];
__device__ float  g_wch[B*C];
__device__ float2 g_part[CSPLIT][B*HW]; // partial (max,sum) per channel-chunk
__device__ float2 g_cat2[B*HW];         // interleaved (maxmap, avgmap) per pixel
__device__ float  g_ws[B*HW];

// ---- packed f32x2 helpers (sm_100+) ----
__device__ __forceinline__ ull pack2(float a, float b) {
    ull r; asm("mov.b64 %0, {%1, %2};" : "=l"(r) : "f"(a), "f"(b)); return r;
}
__device__ __forceinline__ float2 unpack2(ull v) {
    float2 r; asm("mov.b64 {%0, %1}, %2;" : "=f"(r.x), "=f"(r.y) : "l"(v)); return r;
}
__device__ __forceinline__ ull ffma2(ull a, ull b, ull c) {
    ull d; asm("fma.rn.f32x2 %0, %1, %2, %3;" : "=l"(d) : "l"(a), "l"(b), "l"(c)); return d;
}
// streaming (evict-first) float4 load/store
__device__ __forceinline__ float4 ldcs4(const float4* p) {
    float4 v;
    asm("ld.global.cs.v4.f32 {%0,%1,%2,%3}, [%4];"
        : "=f"(v.x), "=f"(v.y), "=f"(v.z), "=f"(v.w) : "l"(p));
    return v;
}
__device__ __forceinline__ void stcs4(float4* p, float4 v) {
    asm volatile("st.global.cs.v4.f32 [%0], {%1,%2,%3,%4};"
                 :: "l"(p), "f"(v.x), "f"(v.y), "f"(v.z), "f"(v.w));
}

// ---------------- K1: per-(b,c) mean & max over H,W ----------------
__global__ __launch_bounds__(256) void k_reduce_hw(const float* __restrict__ x) {
    int bc = blockIdx.x;
    const float4* xp = (const float4*)(x + (size_t)bc * HW);
    float s0 = 0.f, s1 = 0.f, m0 = -INFINITY, m1 = -INFINITY;
    #pragma unroll 4
    for (int i = threadIdx.x; i < HW/8; i += blockDim.x) {
        float4 v = ldcs4(&xp[i]);
        float4 u = ldcs4(&xp[i + HW/8]);
        s0 += (v.x + v.y) + (v.z + v.w);
        s1 += (u.x + u.y) + (u.z + u.w);
        m0 = fmaxf(m0, fmaxf(fmaxf(v.x, v.y), fmaxf(v.z, v.w)));
        m1 = fmaxf(m1, fmaxf(fmaxf(u.x, u.y), fmaxf(u.z, u.w)));
    }
    float s = s0 + s1, m = fmaxf(m0, m1);
    #pragma unroll
    for (int o = 16; o; o >>= 1) {
        s += __shfl_xor_sync(0xffffffffu, s, o);
        m = fmaxf(m, __shfl_xor_sync(0xffffffffu, m, o));
    }
    __shared__ float ss[8], sm[8];
    int w = threadIdx.x >> 5, l = threadIdx.x & 31;
    if (l == 0) { ss[w] = s; sm[w] = m; }
    __syncthreads();
    if (threadIdx.x == 0) {
        for (int i = 1; i < 8; i++) { s += ss[i]; m = fmaxf(m, sm[i]); }
        g_avg[bc] = s * (1.f / HW);
        g_max[bc] = m;
    }
}

// ---------------- K2: channel MLP -> wch (tiny, grid=B) ----------------
__global__ __launch_bounds__(256) void k_mlp(const float* __restrict__ w1, const float* __restrict__ b1,
                                             const float* __restrict__ w2, const float* __restrict__ b2) {
    int b = blockIdx.x;
    int t = threadIdx.x;
    __shared__ float s_avg[C], s_mx[C], s_h[R];
    s_avg[t] = g_avg[b*C + t];
    s_mx[t]  = g_max[b*C + t];
    __syncthreads();
    if (t < R) {
        float ha = b1[t], hm = b1[t];
        #pragma unroll 8
        for (int c = 0; c < C; c++) {
            float w = __ldg(&w1[t*C + c]);
            ha = fmaf(w, s_avg[c], ha);
            hm = fmaf(w, s_mx[c],  hm);
        }
        s_h[t] = fmaxf(ha, 0.f) + fmaxf(hm, 0.f);
    }
    __syncthreads();
    float o = 2.f * __ldg(&b2[t]);
    #pragma unroll
    for (int r = 0; r < R; r++) o = fmaf(__ldg(&w2[t*R + r]), s_h[r], o);
    g_wch[b*C + t] = 1.f / (1.f + __expf(-o));
}

// ---------------- K3: partial cat maps over 64 channels ----------------
// grid (HW/4/256, B, CSPLIT), block 256
__global__ __launch_bounds__(256) void k_cat(const float* __restrict__ x) {
    int b  = blockIdx.y;
    int cz = blockIdx.z;
    int t  = threadIdx.x;
    __shared__ float sw[CCHUNK];
    if (t < CCHUNK) sw[t] = g_wch[b*C + cz*CCHUNK + t];
    __syncthreads();

    int p4 = blockIdx.x * blockDim.x + t;   // float4 index within HW
    const float4* xb = (const float4*)(x + (size_t)b * C * HW + (size_t)cz*CCHUNK*HW);
    float4 s = make_float4(0.f, 0.f, 0.f, 0.f);
    float4 m = make_float4(-INFINITY, -INFINITY, -INFINITY, -INFINITY);
    #pragma unroll 8
    for (int c = 0; c < CCHUNK; c++) {
        float4 v = ldcs4(&xb[(size_t)c * (HW/4) + p4]);
        float w = sw[c];
        float a0 = w*v.x, a1 = w*v.y, a2 = w*v.z, a3 = w*v.w;
        s.x += a0; s.y += a1; s.z += a2; s.w += a3;
        m.x = fmaxf(m.x, a0); m.y = fmaxf(m.y, a1);
        m.z = fmaxf(m.z, a2); m.w = fmaxf(m.w, a3);
    }
    float4* dst = (float4*)(g_part[cz] + (size_t)b*HW + (size_t)p4*4);
    dst[0] = make_float4(m.x, s.x, m.y, s.y);
    dst[1] = make_float4(m.z, s.z, m.w, s.w);
}

// ---------------- K3b: combine the CSPLIT partials -> g_cat2 ----------------
__global__ __launch_bounds__(256) void k_combine() {
    int i = blockIdx.x * blockDim.x + threadIdx.x;   // 0 .. B*HW/2-1
    float4 a = ((const float4*)g_part[0])[i];
    float4 c = ((const float4*)g_part[1])[i];
    float4 d = ((const float4*)g_part[2])[i];
    float4 e = ((const float4*)g_part[3])[i];
    const float inv = 1.f / C;
    float4 o;
    o.x = fmaxf(fmaxf(a.x, c.x), fmaxf(d.x, e.x));
    o.y = ((a.y + c.y) + (d.y + e.y)) * inv;
    o.z = fmaxf(fmaxf(a.z, c.z), fmaxf(d.z, e.z));
    o.w = ((a.w + c.w) + (d.w + e.w)) * inv;
    ((float4*)g_cat2)[i] = o;
}

// ---------------- K4: offsets conv + deform conv + BN + sigmoid -> ws ----------------
// 2 pixels per thread (rows i0, i0+1), shared neighborhood rows, each weight
// LDS feeds two FFMA2s. grid = B*H/2, block = 128.
__global__ __launch_bounds__(128)
void k_deform(const float* __restrict__ off_w, const float* __restrict__ off_b,
              const float* __restrict__ dc_w,  const float* __restrict__ dc_b,
              const float* __restrict__ bn_gamma, const float* __restrict__ bn_beta,
              const float* __restrict__ bn_mean,  const float* __restrict__ bn_var) {
    __shared__ ull   s_wp[9][18];     // [tap][q] = (w_dy[q], w_dx[q])
    __shared__ ull   s_obp[9];        // (off_b[2k], off_b[2k+1])
    __shared__ float s_dw[18];
    __shared__ float2 trow[4][W];     // rows i0-1 .. i0+2 of (max,avg)

    int b  = blockIdx.x >> 6;
    int i0 = (blockIdx.x & 63) * 2;
    int j  = threadIdx.x;

    for (int t = threadIdx.x; t < 162; t += 128) {
        int k = t / 18, q = t - k*18;
        s_wp[k][q] = pack2(off_w[(2*k)*18 + q], off_w[(2*k+1)*18 + q]);
    }
    if (threadIdx.x < 9)  s_obp[threadIdx.x] = pack2(off_b[2*threadIdx.x], off_b[2*threadIdx.x + 1]);
    if (threadIdx.x < 18) s_dw[threadIdx.x]  = dc_w[threadIdx.x];

    const float2* c2 = g_cat2 + (size_t)b*HW;

    #pragma unroll
    for (int r = 0; r < 4; r++) {
        int yy = i0 + r - 1;
        bool ok = (unsigned)yy < H;
        trow[r][j] = ok ? c2[yy*W + j] : make_float2(0.f, 0.f);
    }
    __syncthreads();

    // duplicated packed neighborhood: 4 rows x 3 cols, 2 channels
    ull na[4][3], nb[4][3];
    #pragma unroll
    for (int u = 0; u < 4; u++) {
        #pragma unroll
        for (int v = 0; v < 3; v++) {
            int xx = j + v - 1;
            bool ok = (unsigned)xx < W;
            int xc = min(max(xx, 0), W-1);
            float2 val = trow[u][xc];
            float vx = ok ? val.x : 0.f;
            float vy = ok ? val.y : 0.f;
            na[u][v] = pack2(vx, vx);
            nb[u][v] = pack2(vy, vy);
        }
    }

    const float dcb = __ldg(dc_b);
    float acc0 = dcb, acc1 = dcb;
    const float fj = (float)j;
    const float fi0 = (float)i0, fi1 = (float)(i0 + 1);

    #pragma unroll
    for (int k = 0; k < 9; k++) {
        const int ky = k / 3, kx = k % 3;
        ull a0 = s_obp[k], a1 = a0;
        #pragma unroll
        for (int q = 0; q < 9; q++) {
            int u = q / 3, v = q - u*3;
            ull w = s_wp[k][q];
            a0 = ffma2(w, na[u][v],     a0);
            a1 = ffma2(w, na[u + 1][v], a1);
        }
        #pragma unroll
        for (int q = 0; q < 9; q++) {
            int u = q / 3, v = q - u*3;
            ull w = s_wp[k][9 + q];
            a0 = ffma2(w, nb[u][v],     a0);
            a1 = ffma2(w, nb[u + 1][v], a1);
        }
        float2 o0 = unpack2(a0);   // (dy, dx) pixel row i0
        float2 o1 = unpack2(a1);   // pixel row i0+1

        #pragma unroll
        for (int p = 0; p < 2; p++) {
            float py = (p ? fi1 : fi0) + (float)(ky - 1) + (p ? o1.x : o0.x);
            float px = fj + (float)(kx - 1) + (p ? o1.y : o0.y);
            float y0f = floorf(py), x0f = floorf(px);
            float wy = py - y0f, wx = px - x0f;
            float omwy = 1.f - wy, omwx = 1.f - wx;
            int y0 = (int)y0f, x0 = (int)x0f;

            ull sacc = 0ull;
            #pragma unroll
            for (int dy = 0; dy < 2; dy++) {
                #pragma unroll
                for (int dx = 0; dx < 2; dx++) {
                    int yi = y0 + dy, xi = x0 + dx;
                    bool ok = ((unsigned)yi < H) & ((unsigned)xi < W);
                    float wgt = (dy ? wy : omwy) * (dx ? wx : omwx);
                    wgt = ok ? wgt : 0.f;
                    int idx = min(max(yi, 0), H-1) * W + min(max(xi, 0), W-1);
                    ull v = *(const ull*)(c2 + idx);
                    sacc = ffma2(v, pack2(wgt, wgt), sacc);
                }
            }
            float2 sv = unpack2(sacc);
            if (p) {
                acc1 = fmaf(sv.x, s_dw[k],     acc1);
                acc1 = fmaf(sv.y, s_dw[9 + k], acc1);
            } else {
                acc0 = fmaf(sv.x, s_dw[k],     acc0);
                acc0 = fmaf(sv.y, s_dw[9 + k], acc0);
            }
        }
    }

    float inv = __ldg(bn_gamma) * rsqrtf(__ldg(bn_var) + 1e-5f);
    float mean = __ldg(bn_mean), beta = __ldg(bn_beta);
    float d0 = (acc0 - mean) * inv + beta;
    float d1 = (acc1 - mean) * inv + beta;
    g_ws[b*HW + i0*W + j]       = 1.f / (1.f + __expf(-d0));
    g_ws[b*HW + (i0+1)*W + j]   = 1.f / (1.f + __expf(-d1));
}

// ---------------- K5: out = x * (1 + wch*ws) ----------------
__global__ __launch_bounds__(256) void k_final(const float* __restrict__ x, float* __restrict__ out) {
    size_t base = (size_t)blockIdx.x * 512 + threadIdx.x;   // float4 index
    size_t e    = base << 2;
    int b  = (int)(e >> 22);            // C*HW = 2^22
    int c  = (int)(e >> 14) & (C - 1);  // uniform across the block
    float w = __ldg(&g_wch[b*C + c]);

    int hw0 = (int)e & (HW - 1);
    const float4* wsp = (const float4*)(g_ws + (size_t)b*HW);

    float4 xv0  = ldcs4((const float4*)x + base);
    float4 xv1  = ldcs4((const float4*)x + base + 256);
    float4 ws0  = __ldg(&wsp[hw0 >> 2]);
    float4 ws1  = __ldg(&wsp[(hw0 + 1024) >> 2]);

    float4 o0, o1;
    o0.x = xv0.x * fmaf(w, ws0.x, 1.f);
    o0.y = xv0.y * fmaf(w, ws0.y, 1.f);
    o0.z = xv0.z * fmaf(w, ws0.z, 1.f);
    o0.w = xv0.w * fmaf(w, ws0.w, 1.f);
    o1.x = xv1.x * fmaf(w, ws1.x, 1.f);
    o1.y = xv1.y * fmaf(w, ws1.y, 1.f);
    o1.z = xv1.z * fmaf(w, ws1.z, 1.f);
    o1.w = xv1.w * fmaf(w, ws1.w, 1.f);
    stcs4((float4*)out + base,       o0);
    stcs4((float4*)out + base + 256, o1);
}

extern "C" void kernel_launch(void* const* d_in, const int* in_sizes, int n_in,
                              void* d_out, int out_size) {
    const float* x     = (const float*)d_in[0];
    const float* w1    = (const float*)d_in[1];
    const float* b1    = (const float*)d_in[2];
    const float* w2    = (const float*)d_in[3];
    const float* b2    = (const float*)d_in[4];
    const float* off_w = (const float*)d_in[5];
    const float* off_b = (const float*)d_in[6];
    const float* dc_w  = (const float*)d_in[7];
    const float* dc_b  = (const float*)d_in[8];
    const float* bng   = (const float*)d_in[9];
    const float* bnb   = (const float*)d_in[10];
    const float* bnm   = (const float*)d_in[11];
    const float* bnv   = (const float*)d_in[12];
    float* out = (float*)d_out;

    k_reduce_hw<<<B*C, 256>>>(x);
    k_mlp<<<B, C>>>(w1, b1, w2, b2);
    {
        dim3 grid(HW/4/256, B, CSPLIT);
        k_cat<<<grid, 256>>>(x);
    }
    k_combine<<<(B*HW/2)/256, 256>>>();
    k_deform<<<B*H/2, 128>>>(off_w, off_b, dc_w, dc_b, bng, bnb, bnm, bnv);
    k_final<<<(B*C*HW)/4/512, 256>>>(x, out);
}